// round 9
// baseline (speedup 1.0000x reference)
#include <cuda_runtime.h>
#include <cuda_bf16.h>

#define NCLASS 100
#define NCPAD  101
#define NFEAT  64
#define GROUPS 4
#define TPB    256
#define CP     (NCLASS * NFEAT)
#define CPP    (NCPAD * NFEAT)
#define BATCH  16

__device__ float2       g_acc[CP];
__device__ unsigned int g_cnt[NCLASS];

__global__ void zero_kernel() {
    int i = blockIdx.x * blockDim.x + threadIdx.x;
    if (i < CP) g_acc[i] = make_float2(0.f, 0.f);
    if (i < NCLASS) g_cnt[i] = 0u;
}

// 64-thread group owns a private smem float2 acc[101][64]; thread p owns
// column p (race-free plain RMW). DEPTH-3 pipeline: two chunks of (c,v)
// are always in flight (~33 outstanding LDGs/warp) so the ~700-cyc DRAM
// latency is covered -> kernel becomes DRAM-throughput bound.
__global__ void __launch_bounds__(TPB, 1)
accum_kernel(const float* __restrict__ x, const int* __restrict__ t, int nrows) {
    extern __shared__ float2 smem[];
    const int group = threadIdx.x >> 6;
    const int p     = threadIdx.x & 63;
    const int w     = (threadIdx.x >> 5) & 1;
    const int l     = threadIdx.x & 31;
    float2* acc = smem + group * CPP;
    unsigned int* cnt = (unsigned int*)(smem + GROUPS * CPP);

    for (int i = threadIdx.x; i < GROUPS * CPP; i += TPB) smem[i] = make_float2(0.f, 0.f);
    for (int i = threadIdx.x; i < NCLASS; i += TPB) cnt[i] = 0u;
    __syncthreads();

    const int gid     = blockIdx.x * GROUPS + group;
    const int ngroups = gridDim.x * GROUPS;
    const int nchunks = (nrows + BATCH - 1) / BATCH;

    float v0[BATCH], v1[BATCH], v2[BATCH];
    int c0, c1, c2;

    auto load_chunk = [&](int ci, int& c_lane, float* v) {
        const int r0 = ci * BATCH;
        const int nv = min(BATCH, nrows - r0);
        c_lane = 0;
        if (l < nv) c_lane = __ldcs(t + r0 + l);           // one 64B coalesced LDG
        if (w == 0 && l < nv) atomicAdd(&cnt[c_lane], 1u); // spread-addr ATOMS
        if (nv == BATCH) {
            #pragma unroll
            for (int b = 0; b < BATCH; b++)
                v[b] = __ldcs(x + (size_t)(r0 + b) * NFEAT + p);
        } else {
            #pragma unroll
            for (int b = 0; b < BATCH; b++)
                v[b] = (b < nv) ? __ldcs(x + (size_t)(r0 + b) * NFEAT + p) : 0.f;
        }
    };

    auto accum_chunk = [&](int c_lane, const float* v) {
        int carr[BATCH];
        #pragma unroll
        for (int b = 0; b < BATCH; b++)
            carr[b] = __shfl_sync(0xffffffffu, c_lane, b);
        #pragma unroll
        for (int b = 0; b < BATCH; b += 2) {
            const float va = v[b], vb = v[b + 1];
            const bool dup = (carr[b] == carr[b + 1]);
            const int idx0 = carr[b] * NFEAT + p;
            const int idx1 = (dup ? NCLASS : carr[b + 1]) * NFEAT + p;
            const float qb  = vb * vb;
            const float s0  = va + (dup ? vb : 0.f);
            const float q0  = fmaf(va, va, dup ? qb : 0.f);
            const float s1  = dup ? 0.f : vb;
            const float q1  = dup ? 0.f : qb;
            float2 a0 = acc[idx0];
            float2 a1 = acc[idx1];
            a0.x += s0;  a0.y += q0;
            a1.x += s1;  a1.y += q1;
            acc[idx0] = a0;
            acc[idx1] = a1;
        }
    };

    // Depth-3 rotated pipeline: load(ca+2ng) in flight while accum(ca).
    int ca = gid;                    // next chunk to accumulate
    int cl = gid + 2 * ngroups;      // next chunk to load
    bool run = ca < nchunks;
    if (run)                    load_chunk(ca, c0, v0);
    if (ca + ngroups < nchunks) load_chunk(ca + ngroups, c1, v1);
    while (run) {
        if (cl < nchunks) load_chunk(cl, c2, v2);
        cl += ngroups;
        accum_chunk(c0, v0);
        ca += ngroups; run = ca < nchunks;
        if (!run) break;

        if (cl < nchunks) load_chunk(cl, c0, v0);
        cl += ngroups;
        accum_chunk(c1, v1);
        ca += ngroups; run = ca < nchunks;
        if (!run) break;

        if (cl < nchunks) load_chunk(cl, c1, v1);
        cl += ngroups;
        accum_chunk(c2, v2);
        ca += ngroups; run = ca < nchunks;
    }
    __syncthreads();

    for (int i = threadIdx.x; i < CP; i += TPB) {
        float ts = 0.f, tss = 0.f;
        #pragma unroll
        for (int g = 0; g < GROUPS; g++) {
            ts  += smem[g * CPP + i].x;
            tss += smem[g * CPP + i].y;
        }
        atomicAdd(&g_acc[i].x, ts);
        atomicAdd(&g_acc[i].y, tss);
    }
    for (int i = threadIdx.x; i < NCLASS; i += TPB)
        atomicAdd(&g_cnt[i], cnt[i]);
}

__global__ void final_kernel(float* __restrict__ out) {
    __shared__ double red[256];
    double accd = 0.0;
    for (int i = threadIdx.x; i < CP; i += 256) {
        const int c = i / NFEAT;
        const double n  = (double)g_cnt[c];
        const double s  = (double)g_acc[i].x;
        const double ss = (double)g_acc[i].y;
        accd += (ss - s * s / n) / (n - 1.0);
    }
    red[threadIdx.x] = accd;
    __syncthreads();
    #pragma unroll
    for (int off = 128; off > 0; off >>= 1) {
        if ((int)threadIdx.x < off) red[threadIdx.x] += red[threadIdx.x + off];
        __syncthreads();
    }
    if (threadIdx.x == 0) out[0] = (float)(red[0] / (double)NCLASS);
}

extern "C" void kernel_launch(void* const* d_in, const int* in_sizes, int n_in,
                              void* d_out, int out_size) {
    const float* x = (const float*)d_in[0];   // (N, 64) fp32
    const int*   t = (const int*)d_in[1];     // (N,)    int32
    const int nrows = in_sizes[0] / NFEAT;
    float* out = (float*)d_out;

    int nsm = 148;
    cudaDeviceGetAttribute(&nsm, cudaDevAttrMultiProcessorCount, 0);

    const size_t smem_bytes = (size_t)GROUPS * CPP * sizeof(float2)
                            + (size_t)NCLASS * sizeof(unsigned int);
    cudaFuncSetAttribute(accum_kernel, cudaFuncAttributeMaxDynamicSharedMemorySize,
                         (int)smem_bytes);

    zero_kernel<<<(CP + 255) / 256, 256>>>();
    accum_kernel<<<nsm, TPB, smem_bytes>>>(x, t, nrows);
    final_kernel<<<1, 256>>>(out);
}